// round 10
// baseline (speedup 1.0000x reference)
#include <cuda_runtime.h>
#include <cuda_bf16.h>
#include <cstdint>

// SeparationLoss: mean over B of sum_{i!=j} max(0, thr2 - ||kp_i - kp_j||^2)
// Input: batched_kps [B, 17, 3] f32 (B = 131072). Output: scalar f32.
//
// R10: software-pipelined blocks. Each block owns 2 tiles of 64 rows with
// double-buffered cp.async.bulk: both copies issued up front, tile-1 copy
// overlaps tile-0 compute (previously copy->wait->compute was fully serial
// and the DRAM burst was exposed). Gram-identity core (R8). Release/acquire
// atomic replaces threadfence in the fused last-block reduction.

#define J 17
#define ROW_F 51                    // 17*3 floats per row
#define TILE_ROWS 64
#define THREADS 64
#define GRID_MAX 1024
#define TILE_BYTES (TILE_ROWS * ROW_F * 4)    // 13056
#define NBLOCKS_MAX 8192

__device__ __align__(16) float g_partials[NBLOCKS_MAX];
__device__ unsigned int g_done_count;   // zero-init; inc wraps -> self-resets per run

__device__ __forceinline__ uint32_t smem_u32(const void* p) {
    uint32_t a;
    asm("{ .reg .u64 t; cvta.to.shared.u64 t, %1; cvt.u32.u64 %0, t; }"
        : "=r"(a) : "l"(p));
    return a;
}

__device__ __forceinline__ void mbar_wait(uint32_t mb, uint32_t parity) {
    uint32_t done;
    asm volatile(
        "{\n\t.reg .pred p;\n\t"
        "mbarrier.try_wait.parity.acquire.cta.shared::cta.b64 p, [%1], %2;\n\t"
        "selp.b32 %0, 1, 0, p;\n\t}"
        : "=r"(done) : "r"(mb), "r"(parity) : "memory");
    if (!done) {
        asm volatile(
            "{\n\t.reg .pred P1;\n\t"
            "W_%=:\n\t"
            "mbarrier.try_wait.parity.acquire.cta.shared::cta.b64 P1, [%0], %1, 0x989680;\n\t"
            "@P1 bra.uni D_%=;\n\t"
            "bra.uni W_%=;\n\t"
            "D_%=:\n\t}"
            :: "r"(mb), "r"(parity) : "memory");
    }
}

__device__ __forceinline__ void issue_bulk(uint32_t mb, uint32_t smem_dst,
                                           const float* gsrc) {
    asm volatile("mbarrier.arrive.expect_tx.shared.b64 _, [%0], %1;"
                 :: "r"(mb), "r"((uint32_t)TILE_BYTES) : "memory");
    asm volatile(
        "cp.async.bulk.shared::cta.global.mbarrier::complete_tx::bytes "
        "[%0], [%1], %2, [%3];"
        :: "r"(smem_dst), "l"(gsrc), "r"((uint32_t)TILE_BYTES), "r"(mb)
        : "memory");
}

__global__ __launch_bounds__(THREADS, 8)
void sep_loss_fused(const float* __restrict__ kps, int B, int grid, int ntilesTotal,
                    float invB, float* __restrict__ out) {
    __shared__ __align__(16) float s[2][TILE_ROWS * ROW_F];   // 2 x 13056 B
    __shared__ __align__(8)  unsigned long long mbar[2];
    __shared__ float wsum[THREADS / 32];
    __shared__ bool  isLast;

    const int tid = threadIdx.x;
    const int blk = blockIdx.x;
    const uint32_t mb0 = smem_u32(&mbar[0]);
    // tiles handled by this block: t = blk, blk+grid, blk+2*grid, ...
    const int nt = (ntilesTotal - blk + grid - 1) / grid;

    if (tid == 0) {
        asm volatile("mbarrier.init.shared.b64 [%0], %1;" :: "r"(mb0), "r"(1) : "memory");
        asm volatile("mbarrier.init.shared.b64 [%0], %1;" :: "r"(mb0 + 8), "r"(1) : "memory");
    }
    __syncthreads();

    // prologue: issue copies for tiles 0 and 1 (full tiles only)
    if (tid == 0) {
        #pragma unroll
        for (int it = 0; it < 2; it++) {
            if (it < nt) {
                int tIdx = blk + it * grid;
                if ((tIdx + 1) * TILE_ROWS <= B)   // full tile
                    issue_bulk(mb0 + 8u * it, smem_u32(s[it]),
                               kps + (size_t)tIdx * TILE_ROWS * ROW_F);
            }
        }
    }
    __syncthreads();   // manual-staging path below needs everyone past issue

    float a0 = 0.0f, a1 = 0.0f;

    for (int it = 0; it < nt; it++) {
        const int buf = it & 1;
        const int tIdx = blk + it * grid;
        const int rowBase = tIdx * TILE_ROWS;
        const int rowsHere = min(TILE_ROWS, B - rowBase);
        const float* __restrict__ sb = s[buf];

        if (rowsHere == TILE_ROWS) {
            mbar_wait(mb0 + 8u * buf, (uint32_t)((it >> 1) & 1));
        } else {
            // partial tail tile: manual staging (no bulk was issued)
            const float* src = kps + (size_t)rowBase * ROW_F;
            for (int i = tid; i < rowsHere * ROW_F; i += THREADS)
                s[buf][i] = src[i];
            __syncthreads();
        }

        if (tid < rowsHere) {
            const float* __restrict__ rp = sb + tid * ROW_F;
            float p[ROW_F];
            float g[J];
            #pragma unroll
            for (int c = 0; c < ROW_F; c++) p[c] = rp[c];
            #pragma unroll
            for (int i = 0; i < J; i++) {
                float x = p[3*i], y = p[3*i+1], z = p[3*i+2];
                float r = fmaf(z, z, fmaf(y, y, x * x));
                g[i] = fmaf(r, -0.5f, 0.0025f);      // 0.25*thr2; FFMA-imm
            }
            int k = 0;
            #pragma unroll
            for (int i = 0; i < J; i++) {
                #pragma unroll
                for (int j = i + 1; j < J; j++) {
                    // d = 0.5*(thr2 - d2_ij) = g_i + g_j + dot(p_i, p_j)
                    float w = g[i] + g[j];
                    float d = fmaf(p[3*i+2], p[3*j+2],
                              fmaf(p[3*i+1], p[3*j+1],
                              fmaf(p[3*i  ], p[3*j  ], w)));
                    float h = fmaxf(d, 0.0f);
                    if (k & 1) a1 += h; else a0 += h;
                    k++;
                }
            }
        }

        // reissue pipeline for tile it+2 (only when nt > 2; bench has nt = 2)
        if (it + 2 < nt) {
            __syncthreads();   // everyone done reading buf before overwrite
            if (tid == 0) {
                int nIdx = blk + (it + 2) * grid;
                if ((nIdx + 1) * TILE_ROWS <= B)
                    issue_bulk(mb0 + 8u * buf, smem_u32(s[buf]),
                               kps + (size_t)nIdx * TILE_ROWS * ROW_F);
            }
            __syncthreads();
        }
    }

    // hinge = 2*max(0,d); ordered pairs double again -> x4
    float acc = (a0 + a1) * 4.0f;

    // ---- deterministic block reduction (2 warps) ----
    #pragma unroll
    for (int off = 16; off > 0; off >>= 1)
        acc += __shfl_down_sync(0xFFFFFFFFu, acc, off);
    if ((tid & 31) == 0) wsum[tid >> 5] = acc;
    __syncthreads();

    if (tid == 0) {
        g_partials[blk] = wsum[0] + wsum[1];
        // release-inc orders the store above; acquire side read by last block.
        unsigned int c;
        asm volatile("atom.acq_rel.gpu.global.inc.u32 %0, [%1], %2;"
                     : "=r"(c)
                     : "l"(&g_done_count), "r"((unsigned int)(grid - 1))
                     : "memory");
        isLast = (c == (unsigned int)(grid - 1));
    }
    __syncthreads();

    // ---- last block: vectorized fixed-order final reduction ----
    if (isLast) {
        float v = 0.0f;
        const int nvec = grid >> 2;              // 256 for grid=1024
        const float4* gp = reinterpret_cast<const float4*>(g_partials);
        #pragma unroll 4
        for (int i = tid; i < nvec; i += THREADS) {
            float4 f = gp[i];
            v += (f.x + f.y) + (f.z + f.w);
        }
        for (int i = (nvec << 2) + tid; i < grid; i += THREADS)
            v += g_partials[i];
        #pragma unroll
        for (int off = 16; off > 0; off >>= 1)
            v += __shfl_down_sync(0xFFFFFFFFu, v, off);
        if ((tid & 31) == 0) wsum[tid >> 5] = v;
        __syncthreads();
        if (tid == 0)
            out[0] = (wsum[0] + wsum[1]) * invB;
    }
}

extern "C" void kernel_launch(void* const* d_in, const int* in_sizes, int n_in,
                              void* d_out, int out_size) {
    const float* kps = (const float*)d_in[0];
    const int B = in_sizes[0] / ROW_F;
    const int ntiles = (B + TILE_ROWS - 1) / TILE_ROWS;   // 2048 for B=131072
    const int grid = ntiles < GRID_MAX ? ntiles : GRID_MAX;  // 1024

    sep_loss_fused<<<grid, THREADS>>>(kps, B, grid, ntiles, 1.0f / (float)B,
                                      (float*)d_out);
}

// round 12
// speedup vs baseline: 1.1380x; 1.1380x over previous
#include <cuda_runtime.h>
#include <cuda_bf16.h>
#include <cstdint>

// SeparationLoss: mean over B of sum_{i!=j} max(0, thr2 - ||kp_i - kp_j||^2)
// Input: batched_kps [B, 17, 3] f32 (B = 131072). Output: scalar f32.
//
// R12: no-staging, alignment-fixed. Rows are 204 B (12 mod 16), so warp w
// takes rows ≡ w (mod 4): per-warp-uniform alignment class -> n_lead scalar
// loads, 12 aligned LDG.128, tail scalars, all compile-time indexed (no
// spill). Removes SMEM tile / mbarrier / LDS entirely. Gram-identity core.
// Fused last-block-done reduction with release/acquire atomic.

#define J 17
#define ROW_F 51                    // 17*3 floats per row
#define ROWS_PER_BLOCK 128
#define THREADS 128
#define NBLOCKS_MAX 8192

__device__ __align__(16) float g_partials[NBLOCKS_MAX];
__device__ unsigned int g_done_count;   // zero-init; inc wraps -> self-resets per run

__global__ __launch_bounds__(THREADS, 6)   // 85-reg cap; ~80 demand (R8-measured)
void sep_loss_fused(const float* __restrict__ kps, int B, int nblocks,
                    float invB, float* __restrict__ out) {
    __shared__ float wsum[THREADS / 32];
    __shared__ bool  isLast;

    const int tid  = threadIdx.x;
    const int lane = tid & 31;
    const int wid  = tid >> 5;                       // 0..3 -> alignment class
    const int row  = blockIdx.x * ROWS_PER_BLOCK + 4 * lane + wid;

    float a0 = 0.0f, a1 = 0.0f;
    if (row < B) {
        const float* __restrict__ rf = kps + (size_t)row * ROW_F;
        float p[ROW_F];

        // lead scalars: bring address to 16B boundary. row ≡ wid (mod 4)
        // -> base offset ≡ 12*wid (mod 16) -> n_lead = wid.
        #pragma unroll
        for (int c = 0; c < 3; c++)
            if (c < wid) p[c] = rf[c];               // branch is warp-uniform
        // 12 aligned LDG.128 covering floats [wid, wid+48)
        {
            const float4* __restrict__ v4 =
                reinterpret_cast<const float4*>(rf + wid);
            #pragma unroll
            for (int q = 0; q < 12; q++) {
                float4 v = v4[q];
                p[wid + 4*q + 0] = v.x;
                p[wid + 4*q + 1] = v.y;
                p[wid + 4*q + 2] = v.z;
                p[wid + 4*q + 3] = v.w;
            }
        }
        // tail scalars: floats [wid+48, 51)
        #pragma unroll
        for (int c = 48; c < 51; c++)
            if (c >= wid + 48) p[c] = rf[c];

        float g[J];
        #pragma unroll
        for (int i = 0; i < J; i++) {
            float x = p[3*i], y = p[3*i+1], z = p[3*i+2];
            float r = fmaf(z, z, fmaf(y, y, x * x));
            g[i] = fmaf(r, -0.5f, 0.0025f);          // 0.25*thr2; FFMA-imm
        }

        int k = 0;
        #pragma unroll
        for (int i = 0; i < J; i++) {
            #pragma unroll
            for (int j = i + 1; j < J; j++) {
                // d = 0.5*(thr2 - d2_ij) = g_i + g_j + dot(p_i, p_j)
                float w = g[i] + g[j];
                float d = fmaf(p[3*i+2], p[3*j+2],
                          fmaf(p[3*i+1], p[3*j+1],
                          fmaf(p[3*i  ], p[3*j  ], w)));
                float h = fmaxf(d, 0.0f);            // FMNMX (alu pipe)
                if (k & 1) a1 += h; else a0 += h;
                k++;
            }
        }
    }
    // hinge = 2*max(0,d); ordered pairs double again -> x4
    float acc = (a0 + a1) * 4.0f;

    // ---- deterministic block reduction (4 warps) ----
    #pragma unroll
    for (int off = 16; off > 0; off >>= 1)
        acc += __shfl_down_sync(0xFFFFFFFFu, acc, off);
    if ((tid & 31) == 0) wsum[tid >> 5] = acc;
    __syncthreads();

    if (tid == 0) {
        g_partials[blockIdx.x] = (wsum[0] + wsum[1]) + (wsum[2] + wsum[3]);
        // release-inc orders the store; wraps to 0 at nblocks-1 (replay-safe)
        unsigned int c;
        asm volatile("atom.acq_rel.gpu.global.inc.u32 %0, [%1], %2;"
                     : "=r"(c)
                     : "l"(&g_done_count), "r"((unsigned int)(nblocks - 1))
                     : "memory");
        isLast = (c == (unsigned int)(nblocks - 1));
    }
    __syncthreads();

    // ---- last block: vectorized fixed-order final reduction ----
    if (isLast) {
        float v = 0.0f;
        const int nvec = nblocks >> 2;               // 256 for nblocks=1024
        const float4* gp = reinterpret_cast<const float4*>(g_partials);
        #pragma unroll 2
        for (int i = tid; i < nvec; i += THREADS) {
            float4 f = gp[i];
            v += (f.x + f.y) + (f.z + f.w);
        }
        for (int i = (nvec << 2) + tid; i < nblocks; i += THREADS)
            v += g_partials[i];
        #pragma unroll
        for (int off = 16; off > 0; off >>= 1)
            v += __shfl_down_sync(0xFFFFFFFFu, v, off);
        if ((tid & 31) == 0) wsum[tid >> 5] = v;
        __syncthreads();
        if (tid == 0)
            out[0] = ((wsum[0] + wsum[1]) + (wsum[2] + wsum[3])) * invB;
    }
}

extern "C" void kernel_launch(void* const* d_in, const int* in_sizes, int n_in,
                              void* d_out, int out_size) {
    const float* kps = (const float*)d_in[0];
    const int B = in_sizes[0] / ROW_F;
    const int nblocks = (B + ROWS_PER_BLOCK - 1) / ROWS_PER_BLOCK;  // 1024

    sep_loss_fused<<<nblocks, THREADS>>>(kps, B, nblocks, 1.0f / (float)B,
                                         (float*)d_out);
}

// round 13
// speedup vs baseline: 1.3137x; 1.1544x over previous
#include <cuda_runtime.h>
#include <cuda_bf16.h>
#include <cstdint>

// SeparationLoss: mean over B of sum_{i!=j} max(0, thr2 - ||kp_i - kp_j||^2)
// Input: batched_kps [B, 17, 3] f32 (B = 131072). Output: scalar f32.
//
// R13: static software pipeline. Each block = 2 tiles x 128 rows in two
// fully-unrolled sections with SEPARATE static smem buffers + mbarriers
// (compile-time addressing -> no R10 spill). Both bulk copies issued at t=0:
// tile-B copy overlaps tile-A compute. Grid 512, 4 blocks/SM (smem-limited)
// -> one wave with slack. Gram-identity core. Fused last-block reduction.

#define J 17
#define ROW_F 51                    // 17*3 floats per row
#define TILE_ROWS 128
#define THREADS 128
#define TILE_BYTES (TILE_ROWS * ROW_F * 4)    // 26112
#define NBLOCKS_MAX 8192

__device__ __align__(16) float g_partials[NBLOCKS_MAX];
__device__ unsigned int g_done_count;   // zero-init; inc wraps -> self-resets per run

__device__ __forceinline__ uint32_t smem_u32(const void* p) {
    uint32_t a;
    asm("{ .reg .u64 t; cvta.to.shared.u64 t, %1; cvt.u32.u64 %0, t; }"
        : "=r"(a) : "l"(p));
    return a;
}

__device__ __forceinline__ void mbar_wait0(uint32_t mb) {
    uint32_t done;
    asm volatile(
        "{\n\t.reg .pred p;\n\t"
        "mbarrier.try_wait.parity.acquire.cta.shared::cta.b64 p, [%1], 0;\n\t"
        "selp.b32 %0, 1, 0, p;\n\t}"
        : "=r"(done) : "r"(mb) : "memory");
    if (!done) {
        asm volatile(
            "{\n\t.reg .pred P1;\n\t"
            "W_%=:\n\t"
            "mbarrier.try_wait.parity.acquire.cta.shared::cta.b64 P1, [%0], 0, 0x989680;\n\t"
            "@P1 bra.uni D_%=;\n\t"
            "bra.uni W_%=;\n\t"
            "D_%=:\n\t}"
            :: "r"(mb) : "memory");
    }
}

__device__ __forceinline__ void issue_bulk(uint32_t mb, uint32_t dst,
                                           const float* gsrc) {
    asm volatile("mbarrier.arrive.expect_tx.shared.b64 _, [%0], %1;"
                 :: "r"(mb), "r"((uint32_t)TILE_BYTES) : "memory");
    asm volatile(
        "cp.async.bulk.shared::cta.global.mbarrier::complete_tx::bytes "
        "[%0], [%1], %2, [%3];"
        :: "r"(dst), "l"(gsrc), "r"((uint32_t)TILE_BYTES), "r"(mb)
        : "memory");
}

// Gram-identity pair sum for one row held in SMEM (statically inlined per call
// site -> all addressing compile-time).
__device__ __forceinline__ void row_pairs(const float* __restrict__ rp,
                                          float& a0, float& a1) {
    float p[ROW_F];
    float g[J];
    #pragma unroll
    for (int c = 0; c < ROW_F; c++) p[c] = rp[c];
    #pragma unroll
    for (int i = 0; i < J; i++) {
        float x = p[3*i], y = p[3*i+1], z = p[3*i+2];
        float r = fmaf(z, z, fmaf(y, y, x * x));
        g[i] = fmaf(r, -0.5f, 0.0025f);      // 0.25*thr2; FFMA-imm
    }
    int k = 0;
    #pragma unroll
    for (int i = 0; i < J; i++) {
        #pragma unroll
        for (int j = i + 1; j < J; j++) {
            // d = 0.5*(thr2 - d2_ij) = g_i + g_j + dot(p_i, p_j)
            float w = g[i] + g[j];
            float d = fmaf(p[3*i+2], p[3*j+2],
                      fmaf(p[3*i+1], p[3*j+1],
                      fmaf(p[3*i  ], p[3*j  ], w)));
            float h = fmaxf(d, 0.0f);        // FMNMX (alu pipe)
            if (k & 1) a1 += h; else a0 += h;
            k++;
        }
    }
}

__global__ __launch_bounds__(THREADS, 4)   // smem-limited to 4/SM anyway; 128-reg cap
void sep_loss_fused(const float* __restrict__ kps, int B, int grid,
                    float invB, float* __restrict__ out) {
    __shared__ __align__(16) float sA[TILE_ROWS * ROW_F];   // 26112 B
    __shared__ __align__(16) float sB[TILE_ROWS * ROW_F];   // 26112 B
    __shared__ __align__(8)  unsigned long long mbarA, mbarB;
    __shared__ float wsum[THREADS / 32];
    __shared__ bool  isLast;

    const int tid = threadIdx.x;
    const int blk = blockIdx.x;
    const int rowBaseA = blk * TILE_ROWS;                 // tile A: blk
    const int rowBaseB = (blk + grid) * TILE_ROWS;        // tile B: blk + grid
    const int rowsA = min(TILE_ROWS, max(0, B - rowBaseA));
    const int rowsB = min(TILE_ROWS, max(0, B - rowBaseB));
    const uint32_t mbA = smem_u32(&mbarA), mbB = smem_u32(&mbarB);

    if (tid == 0) {
        asm volatile("mbarrier.init.shared.b64 [%0], 1;" :: "r"(mbA) : "memory");
        asm volatile("mbarrier.init.shared.b64 [%0], 1;" :: "r"(mbB) : "memory");
    }
    __syncthreads();

    // ---- issue BOTH copies up front: tile-B copy overlaps tile-A compute ----
    if (tid == 0) {
        if (rowsA == TILE_ROWS)
            issue_bulk(mbA, smem_u32(sA), kps + (size_t)rowBaseA * ROW_F);
        if (rowsB == TILE_ROWS)
            issue_bulk(mbB, smem_u32(sB), kps + (size_t)rowBaseB * ROW_F);
    }

    float a0 = 0.0f, a1 = 0.0f;

    // ================= section A (static: buffer sA) =================
    if (rowsA == TILE_ROWS) {
        mbar_wait0(mbA);
    } else if (rowsA > 0) {
        const float* src = kps + (size_t)rowBaseA * ROW_F;
        for (int i = tid; i < rowsA * ROW_F; i += THREADS) sA[i] = src[i];
        __syncthreads();
    }
    if (tid < rowsA) row_pairs(sA + tid * ROW_F, a0, a1);

    // ================= section B (static: buffer sB) =================
    if (rowsB == TILE_ROWS) {
        mbar_wait0(mbB);
    } else if (rowsB > 0) {
        const float* src = kps + (size_t)rowBaseB * ROW_F;
        for (int i = tid; i < rowsB * ROW_F; i += THREADS) sB[i] = src[i];
        __syncthreads();
    }
    if (tid < rowsB) row_pairs(sB + tid * ROW_F, a0, a1);

    // hinge = 2*max(0,d); ordered pairs double again -> x4
    float acc = (a0 + a1) * 4.0f;

    // ---- deterministic block reduction (4 warps) ----
    #pragma unroll
    for (int off = 16; off > 0; off >>= 1)
        acc += __shfl_down_sync(0xFFFFFFFFu, acc, off);
    if ((tid & 31) == 0) wsum[tid >> 5] = acc;
    __syncthreads();

    if (tid == 0) {
        g_partials[blk] = (wsum[0] + wsum[1]) + (wsum[2] + wsum[3]);
        // release-inc orders the store; wraps to 0 at grid-1 (replay-safe)
        unsigned int c;
        asm volatile("atom.acq_rel.gpu.global.inc.u32 %0, [%1], %2;"
                     : "=r"(c)
                     : "l"(&g_done_count), "r"((unsigned int)(grid - 1))
                     : "memory");
        isLast = (c == (unsigned int)(grid - 1));
    }
    __syncthreads();

    // ---- last block: 512 partials = 1 float4 per thread ----
    if (isLast) {
        float v = 0.0f;
        const int nvec = grid >> 2;               // 128 for grid=512
        const float4* gp = reinterpret_cast<const float4*>(g_partials);
        for (int i = tid; i < nvec; i += THREADS) {
            float4 f = gp[i];
            v += (f.x + f.y) + (f.z + f.w);
        }
        for (int i = (nvec << 2) + tid; i < grid; i += THREADS)
            v += g_partials[i];
        #pragma unroll
        for (int off = 16; off > 0; off >>= 1)
            v += __shfl_down_sync(0xFFFFFFFFu, v, off);
        if ((tid & 31) == 0) wsum[tid >> 5] = v;
        __syncthreads();
        if (tid == 0)
            out[0] = ((wsum[0] + wsum[1]) + (wsum[2] + wsum[3])) * invB;
    }
}

extern "C" void kernel_launch(void* const* d_in, const int* in_sizes, int n_in,
                              void* d_out, int out_size) {
    const float* kps = (const float*)d_in[0];
    const int B = in_sizes[0] / ROW_F;
    const int ntiles = (B + TILE_ROWS - 1) / TILE_ROWS;   // 1024 for B=131072
    const int grid = (ntiles + 1) / 2;                    // 512: each block = 2 tiles

    sep_loss_fused<<<grid, THREADS>>>(kps, B, grid, 1.0f / (float)B,
                                      (float*)d_out);
}